// round 7
// baseline (speedup 1.0000x reference)
#include <cuda_runtime.h>
#include <cstdint>

#define SZ 512
#define SLAB 128
#define NPLANES 256

// cross-block scratch (allocation-free: __device__ globals)
__device__ float g_colsum[NPLANES][4][SZ];
__device__ float g_snapM[NPLANES][SZ];
__device__ float g_snapA[NPLANES][SZ];
__device__ float g_RT[NPLANES][SZ];
__device__ float g_PM[NPLANES][SZ];
__device__ float g_PA[NPLANES][SZ];
__device__ float g_DA[NPLANES][SZ];
__device__ unsigned int g_cnt[NPLANES];   // zero-init; self-reset each launch

__device__ __forceinline__ uint64_t pack2(float lo, float hi) {
    uint64_t d;
    asm("mov.b64 %0, {%1, %2};" : "=l"(d) : "f"(lo), "f"(hi));
    return d;
}
__device__ __forceinline__ void unpack2(uint64_t d, float& lo, float& hi) {
    asm("mov.b64 {%0, %1}, %2;" : "=f"(lo), "=f"(hi) : "l"(d));
}
__device__ __forceinline__ uint64_t addf32x2(uint64_t a, uint64_t b) {
    uint64_t d;
    asm("add.rn.f32x2 %0, %1, %2;" : "=l"(d) : "l"(a), "l"(b));
    return d;
}

// Reduce 4 independent per-lane values over the warp in 6 shuffles.
// Lane L ends holding the full 32-lane sum of value (L & 3).
__device__ __forceinline__ float multireduce4(float v0, float v1, float v2, float v3, int lane) {
    const unsigned F = 0xffffffffu;
    const bool b0 = lane & 1;
    float x01 = (b0 ? v1 : v0) + __shfl_xor_sync(F, b0 ? v0 : v1, 1);
    float x23 = (b0 ? v3 : v2) + __shfl_xor_sync(F, b0 ? v2 : v3, 1);
    const bool b1 = lane & 2;
    float y = (b1 ? x23 : x01) + __shfl_xor_sync(F, b1 ? x01 : x23, 2);
    y += __shfl_xor_sync(F, y, 4);
    y += __shfl_xor_sync(F, y, 8);
    y += __shfl_xor_sync(F, y, 16);
    return y;
}

__global__ __launch_bounds__(512, 3)
void slab_kernel(const float* __restrict__ x, float* __restrict__ out) {
    __shared__ float sBandRow[4][SLAB];
    __shared__ float sColPart[4][SZ];
    __shared__ float sCutM[SLAB];
    __shared__ float sCutA[SLAB];
    __shared__ float sSnapM[SLAB];
    __shared__ float sSnapA[SLAB];
    __shared__ float sDA[SLAB];
    __shared__ float cA1[SZ], cA2[SZ], cCT[SZ], cRT[SZ], cPM[SZ], cPA[SZ], cDAo[SZ];
    __shared__ bool amLast;

    const int blk = blockIdx.x;
    const int p = blk >> 2;
    const int s = blk & 3;
    const float* __restrict__ X = x + ((size_t)p * SZ + (size_t)s * SLAB) * SZ;

    const int tid  = threadIdx.x;
    const int w    = tid >> 5;
    const int lane = tid & 31;
    const int wr = w >> 2, wc = w & 3;
    const int c0  = wc * 128;
    const int lr0 = wr * 32;
    const bool mainRole = (wc == s);
    const bool antiRole = (wc == 3 - s);

    const float4* __restrict__ base =
        reinterpret_cast<const float4*>(X + (size_t)lr0 * SZ + c0) + lane;
    const int RS4 = SZ / 4;

    uint64_t acc01 = 0ull, acc23 = 0ull;

#pragma unroll
    for (int g = 0; g < 8; ++g) {
        const int lrg = lr0 + 4 * g;

        float4 v0 = __ldcs(base + (4 * g + 0) * RS4);
        float4 v1 = __ldcs(base + (4 * g + 1) * RS4);
        float4 v2 = __ldcs(base + (4 * g + 2) * RS4);
        float4 v3 = __ldcs(base + (4 * g + 3) * RS4);

        float s0, s1, s2, s3;
        {
            uint64_t h0 = addf32x2(pack2(v0.x, v0.y), pack2(v0.z, v0.w));
            uint64_t h1 = addf32x2(pack2(v1.x, v1.y), pack2(v1.z, v1.w));
            uint64_t h2 = addf32x2(pack2(v2.x, v2.y), pack2(v2.z, v2.w));
            uint64_t h3 = addf32x2(pack2(v3.x, v3.y), pack2(v3.z, v3.w));
            float lo, hi;
            unpack2(h0, lo, hi); s0 = lo + hi;
            unpack2(h1, lo, hi); s1 = lo + hi;
            unpack2(h2, lo, hi); s2 = lo + hi;
            unpack2(h3, lo, hi); s3 = lo + hi;
        }

        const float r4 = multireduce4(s0, s1, s2, s3, lane);
        if (lane < 4) sBandRow[wc][lrg + lane] = r4;

        if (mainRole) {
            // cut col for row lrg+u is lrg+u; ls = 8wr+g constant, k = u
            const int ls = 8 * wr + g;
            const bool lt = lane < ls, eq = lane == ls;
            float m0 = lt ? s0 : eq ? v0.x : 0.f;
            float m1 = lt ? s1 : eq ? (v1.x + v1.y) : 0.f;
            float m2 = lt ? s2 : eq ? ((v2.x + v2.y) + v2.z) : 0.f;
            float m3 = (lt | eq) ? s3 : 0.f;
            const float mc = multireduce4(m0, m1, m2, m3, lane);
            if (lane < 4) sCutM[lrg + lane] = mc;
        }
        if (antiRole) {
            // cut col lc = 127-(lrg+u); ls = 31-8wr-g constant, kA = 3-u
            const int ls = 31 - 8 * wr - g;
            const bool lt = lane < ls, eq = lane == ls;
            float m0 = (lt | eq) ? s0 : 0.f;
            float m1 = lt ? s1 : eq ? ((v1.x + v1.y) + v1.z) : 0.f;
            float m2 = lt ? s2 : eq ? (v2.x + v2.y) : 0.f;
            float m3 = lt ? s3 : eq ? v3.x : 0.f;
            const float mc = multireduce4(m0, m1, m2, m3, lane);
            if (lane < 4) sCutA[lrg + lane] = mc;
        }

        // snapshots (strict col prefixes, read acc BEFORE each row's update)
        if (mainRole) {
            const int ls = 8 * wr + g;
            if (lane == ls) {
                float lo, hi;
                unpack2(acc01, lo, hi);
                sSnapM[lrg + 0] = lo;                       // k=0 before row0
                sSnapM[lrg + 1] = hi + v0.y;                // k=1 after row0
                unpack2(acc23, lo, hi);
                sSnapM[lrg + 2] = lo + v0.z + v1.z;         // k=2 after rows0,1
                sSnapM[lrg + 3] = hi + v0.w + v1.w + v2.w;  // k=3 after rows0,1,2
            }
        }
        if (antiRole) {
            const int ls = 31 - 8 * wr - g;
            if (lane == ls) {
                float lo, hi;
                unpack2(acc23, lo, hi);
                sSnapA[127 - (lrg + 0)] = hi;                         // kA=3 before row0
                sSnapA[127 - (lrg + 1)] = lo + v0.z;                  // kA=2 after row0
                unpack2(acc01, lo, hi);
                sSnapA[127 - (lrg + 2)] = hi + v0.y + v1.y;           // kA=1 after rows0,1
                sSnapA[127 - (lrg + 3)] = lo + v0.x + v1.x + v2.x;    // kA=0 after rows0,1,2
                sDA[lrg + 0] = v0.w;
                sDA[lrg + 1] = v1.z;
                sDA[lrg + 2] = v2.y;
                sDA[lrg + 3] = v3.x;
            }
        }

        // packed column-accumulator update (order per component preserved: rows in order)
        acc01 = addf32x2(acc01, addf32x2(addf32x2(pack2(v0.x, v0.y), pack2(v1.x, v1.y)),
                                         addf32x2(pack2(v2.x, v2.y), pack2(v3.x, v3.y))));
        acc23 = addf32x2(acc23, addf32x2(addf32x2(pack2(v0.z, v0.w), pack2(v1.z, v1.w)),
                                         addf32x2(pack2(v2.z, v2.w), pack2(v3.z, v3.w))));
    }

    {
        float a0, a1, a2, a3;
        unpack2(acc01, a0, a1);
        unpack2(acc23, a2, a3);
        reinterpret_cast<float4*>(&sColPart[wr][c0])[lane] = make_float4(a0, a1, a2, a3);
    }
    __syncthreads();

    // ---- slab combine: columns ----
    {
        const int c = tid;
        const float q0 = sColPart[0][c], q1 = sColPart[1][c],
                    q2 = sColPart[2][c], q3 = sColPart[3][c];
        g_colsum[p][s][c] = (q0 + q1) + (q2 + q3);

        const int band = c >> 7;
        if (band == s) {
            const int lr = c - 128 * s;
            const int rg = lr >> 5;
            float sn = sSnapM[lr];
            if (rg > 0) sn += q0;
            if (rg > 1) sn += q1;
            if (rg > 2) sn += q2;
            g_snapM[p][c] = sn;
        }
        if (band == 3 - s) {
            const int la = c - 128 * (3 - s);   // == 127 - lr
            const int rg = (127 - la) >> 5;
            float sn = sSnapA[la];
            if (rg > 0) sn += q0;
            if (rg > 1) sn += q1;
            if (rg > 2) sn += q2;
            g_snapA[p][c] = sn;
        }
    }
    // ---- slab combine: rows ----
    if (tid < SLAB) {
        const int lr = tid;
        const int gr = 128 * s + lr;
        const float b0 = sBandRow[0][lr], b1 = sBandRow[1][lr],
                    b2 = sBandRow[2][lr], b3 = sBandRow[3][lr];
        g_RT[p][gr] = (b0 + b1) + (b2 + b3);

        float pm = sCutM[lr];
        if (s > 0) pm += b0;
        if (s > 1) pm += b1;
        if (s > 2) pm += b2;
        g_PM[p][gr] = pm;

        const int ab = 3 - s;
        float pa = sCutA[lr];
        if (ab > 0) pa += b0;
        if (ab > 1) pa += b1;
        if (ab > 2) pa += b2;
        g_PA[p][gr] = pa;

        g_DA[p][gr] = sDA[lr];
    }

    // ---- last-block-per-plane fused combine ----
    __threadfence();
    __syncthreads();
    if (tid == 0) {
        const unsigned t = atomicAdd(&g_cnt[p], 1u);
        amLast = (t == 3u);
        if (amLast) g_cnt[p] = 0;
    }
    __syncthreads();
    if (!amLast) return;

    {
        const int i = tid;
        const float q0 = g_colsum[p][0][i], q1 = g_colsum[p][1][i],
                    q2 = g_colsum[p][2][i], q3 = g_colsum[p][3][i];
        cCT[i] = (q0 + q1) + (q2 + q3);

        const int jm = i >> 7;
        float a1 = g_snapM[p][i];
        if (jm > 0) a1 += q0;
        if (jm > 1) a1 += q1;
        if (jm > 2) a1 += q2;
        cA1[i] = a1;

        const int ja = (SZ - 1 - i) >> 7;
        float a2 = g_snapA[p][i];
        if (ja > 0) a2 += q0;
        if (ja > 1) a2 += q1;
        if (ja > 2) a2 += q2;
        cA2[i] = a2;

        cRT[i] = g_RT[p][i]; cPM[i] = g_PM[p][i]; cPA[i] = g_PA[p][i]; cDAo[i] = g_DA[p][i];
    }
    __syncthreads();
    {
        const int i = tid;
        const int m = SZ - 1 - i;

        const float tl = cPM[i] + cA1[i];
        const float tr = cRT[i] - cPA[i] + cDAo[i] + cA2[m];
        const float bl = cPA[m] + cCT[i] - cA2[i] - cDAo[m];
        const float br = cRT[m] - cPM[m] + cCT[m] - cA1[m];

        const float inv = 1.0f / (float)(2 * i + 1);
        const int b  = p >> 3;
        const int ch = p & 7;
        float* __restrict__ o = out + ((size_t)(b * SZ + i)) * 32 + ch;
        o[0]  = tl * inv;
        o[8]  = tr * inv;
        o[16] = bl * inv;
        o[24] = br * inv;
    }
}

extern "C" void kernel_launch(void* const* d_in, const int* in_sizes, int n_in,
                              void* d_out, int out_size) {
    const float* x = (const float*)d_in[0];
    float* out = (float*)d_out;
    const int planes = in_sizes[0] / (SZ * SZ);   // 256
    slab_kernel<<<planes * 4, 512>>>(x, out);
}

// round 9
// speedup vs baseline: 1.2235x; 1.2235x over previous
#include <cuda_runtime.h>
#include <cstdint>

#define SZ 512
#define SLAB 64
#define NSLAB 8
#define NPLANES 256

// cross-block scratch (allocation-free: __device__ globals)
__device__ float g_colsum[NPLANES][NSLAB][SZ];
__device__ float g_snapM[NPLANES][SZ];
__device__ float g_snapA[NPLANES][SZ];
__device__ float g_RT[NPLANES][SZ];
__device__ float g_PM[NPLANES][SZ];
__device__ float g_PA[NPLANES][SZ];
__device__ float g_DA[NPLANES][SZ];
__device__ unsigned int g_cnt[NPLANES];   // zero-init; self-reset each launch

__device__ __forceinline__ uint64_t pack2(float lo, float hi) {
    uint64_t d;
    asm("mov.b64 %0, {%1, %2};" : "=l"(d) : "f"(lo), "f"(hi));
    return d;
}
__device__ __forceinline__ void unpack2(uint64_t d, float& lo, float& hi) {
    asm("mov.b64 {%0, %1}, %2;" : "=f"(lo), "=f"(hi) : "l"(d));
}
__device__ __forceinline__ uint64_t addf32x2(uint64_t a, uint64_t b) {
    uint64_t d;
    asm("add.rn.f32x2 %0, %1, %2;" : "=l"(d) : "l"(a), "l"(b));
    return d;
}

// Reduce 8 independent per-lane values over the warp in 9 shuffles.
// Lane L ends holding the full 32-lane sum of value (L & 7).
__device__ __forceinline__ float multireduce8(const float* v, int lane) {
    const unsigned F = 0xffffffffu;
    const bool b0 = lane & 1;
    float x01 = (b0 ? v[1] : v[0]) + __shfl_xor_sync(F, b0 ? v[0] : v[1], 1);
    float x23 = (b0 ? v[3] : v[2]) + __shfl_xor_sync(F, b0 ? v[2] : v[3], 1);
    float x45 = (b0 ? v[5] : v[4]) + __shfl_xor_sync(F, b0 ? v[4] : v[5], 1);
    float x67 = (b0 ? v[7] : v[6]) + __shfl_xor_sync(F, b0 ? v[6] : v[7], 1);
    const bool b1 = lane & 2;
    float y03 = (b1 ? x23 : x01) + __shfl_xor_sync(F, b1 ? x01 : x23, 2);
    float y47 = (b1 ? x67 : x45) + __shfl_xor_sync(F, b1 ? x45 : x67, 2);
    const bool b2 = lane & 4;
    float z = (b2 ? y47 : y03) + __shfl_xor_sync(F, b2 ? y03 : y47, 4);
    z += __shfl_xor_sync(F, z, 8);
    z += __shfl_xor_sync(F, z, 16);
    return z;
}

__global__ __launch_bounds__(512, 2)
void slab_kernel(const float* __restrict__ x, float* __restrict__ out) {
    __shared__ float sBandRow[4][SLAB];   // per-col-band row sums (local rows 0..63)
    __shared__ float sColPart[4][SZ];     // per-rowgroup (16-row) column partials
    __shared__ float sCutM[SLAB];
    __shared__ float sCutA[SLAB];
    __shared__ float sSnapM[SLAB];        // strict col prefix of col gr at row gr (idx lr)
    __shared__ float sSnapA[SLAB];        // strict col prefix of col 511-gr at row gr (idx lr)
    __shared__ float sDA[SLAB];           // x[gr][511-gr] (idx lr)
    __shared__ float cA1[SZ], cA2[SZ], cCT[SZ], cRT[SZ], cPM[SZ], cPA[SZ], cDAo[SZ];
    __shared__ bool amLast;

    const int blk = blockIdx.x;
    const int p = blk >> 3;                    // plane
    const int s = blk & 7;                     // 64-row slab
    const int sh = s & 1;                      // half within 128-col band
    const int sb = s >> 1;                     // column band of main-diag cuts
    const float* __restrict__ X = x + ((size_t)p * SZ + (size_t)s * SLAB) * SZ;

    const int tid  = threadIdx.x;
    const int w    = tid >> 5;
    const int lane = tid & 31;
    const int wr = w >> 2, wc = w & 3;         // 4 rowgroups(16) x 4 col bands(128)
    const int c0  = wc * 128;
    const int lr0 = wr * 16;
    const bool mainRole = (wc == sb);
    const bool antiRole = (wc == 3 - sb);

    const float4* __restrict__ base =
        reinterpret_cast<const float4*>(X + (size_t)lr0 * SZ + c0) + lane;
    const int RS4 = SZ / 4;

    uint64_t acc01 = 0ull, acc23 = 0ull;

#pragma unroll
    for (int g = 0; g < 2; ++g) {
        const int lrg = lr0 + 8 * g;

        float4 v[8];
#pragma unroll
        for (int u = 0; u < 8; u++)
            v[u] = __ldcs(base + (8 * g + u) * RS4);

        float sv[8];
#pragma unroll
        for (int u = 0; u < 8; u++) {
            uint64_t h = addf32x2(pack2(v[u].x, v[u].y), pack2(v[u].z, v[u].w));
            float lo, hi; unpack2(h, lo, hi);
            sv[u] = lo + hi;
        }

        const float r8 = multireduce8(sv, lane);
        if (lane < 8) sBandRow[wc][lrg + lane] = r8;

        if (mainRole) {
            // cut col for row lrg+u is 64*sh + lrg + u; k = u&3
            const int ls0 = 16 * sh + 4 * wr + 2 * g;
            float m[8];
            {
                const bool lt = lane < ls0, eq = lane == ls0;
                m[0] = lt ? sv[0] : eq ? v[0].x : 0.f;
                m[1] = lt ? sv[1] : eq ? (v[1].x + v[1].y) : 0.f;
                m[2] = lt ? sv[2] : eq ? ((v[2].x + v[2].y) + v[2].z) : 0.f;
                m[3] = (lt | eq) ? sv[3] : 0.f;
            }
            {
                const int ls1 = ls0 + 1;
                const bool lt = lane < ls1, eq = lane == ls1;
                m[4] = lt ? sv[4] : eq ? v[4].x : 0.f;
                m[5] = lt ? sv[5] : eq ? (v[5].x + v[5].y) : 0.f;
                m[6] = lt ? sv[6] : eq ? ((v[6].x + v[6].y) + v[6].z) : 0.f;
                m[7] = (lt | eq) ? sv[7] : 0.f;
            }
            const float mc = multireduce8(m, lane);
            if (lane < 8) sCutM[lrg + lane] = mc;
        }
        if (antiRole) {
            // cut col local = 127 - 64*sh - (lrg+u); kA = 3-(u&3)
            const int lsA0 = (127 - 64 * sh - lrg) >> 2;
            float m[8];
            {
                const bool lt = lane < lsA0, eq = lane == lsA0;
                m[0] = (lt | eq) ? sv[0] : 0.f;
                m[1] = lt ? sv[1] : eq ? ((v[1].x + v[1].y) + v[1].z) : 0.f;
                m[2] = lt ? sv[2] : eq ? (v[2].x + v[2].y) : 0.f;
                m[3] = lt ? sv[3] : eq ? v[3].x : 0.f;
            }
            {
                const int lsA1 = lsA0 - 1;
                const bool lt = lane < lsA1, eq = lane == lsA1;
                m[4] = (lt | eq) ? sv[4] : 0.f;
                m[5] = lt ? sv[5] : eq ? ((v[5].x + v[5].y) + v[5].z) : 0.f;
                m[6] = lt ? sv[6] : eq ? (v[6].x + v[6].y) : 0.f;
                m[7] = lt ? sv[7] : eq ? v[7].x : 0.f;
            }
            const float mc = multireduce8(m, lane);
            if (lane < 8) sCutA[lrg + lane] = mc;
        }

        // snapshots (strict col prefixes, read acc BEFORE update) + packed acc update
#pragma unroll
        for (int u = 0; u < 8; u++) {
            const int lr = lrg + u;
            if (mainRole) {
                const int ls = 16 * sh + 4 * wr + 2 * g + (u >> 2);
                if (lane == ls) {
                    float lo, hi, sn;
                    if ((u & 3) < 2) { unpack2(acc01, lo, hi); sn = ((u & 3) == 0) ? lo : hi; }
                    else             { unpack2(acc23, lo, hi); sn = ((u & 3) == 2) ? lo : hi; }
                    sSnapM[lr] = sn;
                }
            }
            if (antiRole) {
                const int lsA = ((127 - 64 * sh - lrg) >> 2) - (u >> 2);
                const int kA = 3 - (u & 3);
                if (lane == lsA) {
                    const float e = (kA == 0) ? v[u].x : (kA == 1) ? v[u].y
                                  : (kA == 2) ? v[u].z : v[u].w;
                    float lo, hi, sn;
                    if (kA < 2) { unpack2(acc01, lo, hi); sn = (kA == 0) ? lo : hi; }
                    else        { unpack2(acc23, lo, hi); sn = (kA == 2) ? lo : hi; }
                    sSnapA[lr] = sn;
                    sDA[lr] = e;
                }
            }
            acc01 = addf32x2(acc01, pack2(v[u].x, v[u].y));
            acc23 = addf32x2(acc23, pack2(v[u].z, v[u].w));
        }
    }

    {
        float a0, a1, a2, a3;
        unpack2(acc01, a0, a1);
        unpack2(acc23, a2, a3);
        reinterpret_cast<float4*>(&sColPart[wr][c0])[lane] = make_float4(a0, a1, a2, a3);
    }
    __syncthreads();

    // ---- slab combine: columns ----
    {
        const int c = tid;
        const float q0 = sColPart[0][c], q1 = sColPart[1][c],
                    q2 = sColPart[2][c], q3 = sColPart[3][c];
        g_colsum[p][s][c] = (q0 + q1) + (q2 + q3);

        if ((c >> 6) == s) {                      // column c == a main-diag row in slab
            const int lr = c - SLAB * s;
            const int rg = lr >> 4;
            float sn = sSnapM[lr];
            if (rg > 0) sn += q0;
            if (rg > 1) sn += q1;
            if (rg > 2) sn += q2;
            g_snapM[p][c] = sn;
        }
        if (((SZ - 1 - c) >> 6) == s) {           // column c == an anti-diag col in slab
            const int lr = (SZ - 1 - c) - SLAB * s;
            const int rg = lr >> 4;
            float sn = sSnapA[lr];
            if (rg > 0) sn += q0;
            if (rg > 1) sn += q1;
            if (rg > 2) sn += q2;
            g_snapA[p][c] = sn;
        }
    }
    // ---- slab combine: rows ----
    if (tid < SLAB) {
        const int lr = tid;
        const int gr = SLAB * s + lr;
        const float b0 = sBandRow[0][lr], b1 = sBandRow[1][lr],
                    b2 = sBandRow[2][lr], b3 = sBandRow[3][lr];
        g_RT[p][gr] = (b0 + b1) + (b2 + b3);

        float pm = sCutM[lr];
        if (sb > 0) pm += b0;
        if (sb > 1) pm += b1;
        if (sb > 2) pm += b2;
        g_PM[p][gr] = pm;

        const int ab = 3 - sb;
        float pa = sCutA[lr];
        if (ab > 0) pa += b0;
        if (ab > 1) pa += b1;
        if (ab > 2) pa += b2;
        g_PA[p][gr] = pa;

        g_DA[p][gr] = sDA[lr];
    }

    // ---- last-block-per-plane fused combine ----
    __threadfence();
    __syncthreads();
    if (tid == 0) {
        const unsigned t = atomicAdd(&g_cnt[p], 1u);
        amLast = (t == NSLAB - 1u);
        if (amLast) g_cnt[p] = 0;
    }
    __syncthreads();
    if (!amLast) return;

    {
        const int i = tid;
        float q[NSLAB];
#pragma unroll
        for (int k = 0; k < NSLAB; k++) q[k] = g_colsum[p][k][i];
        float ct = 0.f;
#pragma unroll
        for (int k = 0; k < NSLAB; k++) ct += q[k];
        cCT[i] = ct;

        const int jm = i >> 6;
        float a1 = g_snapM[p][i];
#pragma unroll
        for (int k = 0; k < NSLAB - 1; k++) if (k < jm) a1 += q[k];
        cA1[i] = a1;

        const int ja = (SZ - 1 - i) >> 6;
        float a2 = g_snapA[p][i];
#pragma unroll
        for (int k = 0; k < NSLAB - 1; k++) if (k < ja) a2 += q[k];
        cA2[i] = a2;

        cRT[i] = g_RT[p][i]; cPM[i] = g_PM[p][i]; cPA[i] = g_PA[p][i]; cDAo[i] = g_DA[p][i];
    }
    __syncthreads();
    {
        const int i = tid;
        const int m = SZ - 1 - i;

        const float tl = cPM[i] + cA1[i];
        const float tr = cRT[i] - cPA[i] + cDAo[i] + cA2[m];
        const float bl = cPA[m] + cCT[i] - cA2[i] - cDAo[m];
        const float br = cRT[m] - cPM[m] + cCT[m] - cA1[m];

        const float inv = 1.0f / (float)(2 * i + 1);
        const int b  = p >> 3;
        const int ch = p & 7;
        float* __restrict__ o = out + ((size_t)(b * SZ + i)) * 32 + ch;
        o[0]  = tl * inv;
        o[8]  = tr * inv;
        o[16] = bl * inv;
        o[24] = br * inv;
    }
}

extern "C" void kernel_launch(void* const* d_in, const int* in_sizes, int n_in,
                              void* d_out, int out_size) {
    const float* x = (const float*)d_in[0];
    float* out = (float*)d_out;
    const int planes = in_sizes[0] / (SZ * SZ);   // 256
    slab_kernel<<<planes * NSLAB, 512>>>(x, out);
}

// round 10
// speedup vs baseline: 1.2286x; 1.0042x over previous
#include <cuda_runtime.h>
#include <cstdint>

#define SZ 512
#define SLAB 128
#define NPLANES 256

// cross-block scratch (allocation-free: __device__ globals)
__device__ float g_colsum[NPLANES][4][SZ];
__device__ float g_snapM[NPLANES][SZ];
__device__ float g_snapA[NPLANES][SZ];
__device__ float g_RT[NPLANES][SZ];
__device__ float g_PM[NPLANES][SZ];
__device__ float g_PA[NPLANES][SZ];
__device__ float g_DA[NPLANES][SZ];
__device__ unsigned int g_cnt[NPLANES];   // zero-init; self-reset each launch

__device__ __forceinline__ uint64_t pack2(float lo, float hi) {
    uint64_t d;
    asm("mov.b64 %0, {%1, %2};" : "=l"(d) : "f"(lo), "f"(hi));
    return d;
}
__device__ __forceinline__ void unpack2(uint64_t d, float& lo, float& hi) {
    asm("mov.b64 {%0, %1}, %2;" : "=f"(lo), "=f"(hi) : "l"(d));
}
__device__ __forceinline__ uint64_t addf32x2(uint64_t a, uint64_t b) {
    uint64_t d;
    asm("add.rn.f32x2 %0, %1, %2;" : "=l"(d) : "l"(a), "l"(b));
    return d;
}

// Reduce 8 independent per-lane values over the warp in 9 shuffles.
// Lane L ends holding the full 32-lane sum of value (L & 7).
__device__ __forceinline__ float multireduce8(const float* v, int lane) {
    const unsigned F = 0xffffffffu;
    const bool b0 = lane & 1;
    float x01 = (b0 ? v[1] : v[0]) + __shfl_xor_sync(F, b0 ? v[0] : v[1], 1);
    float x23 = (b0 ? v[3] : v[2]) + __shfl_xor_sync(F, b0 ? v[2] : v[3], 1);
    float x45 = (b0 ? v[5] : v[4]) + __shfl_xor_sync(F, b0 ? v[4] : v[5], 1);
    float x67 = (b0 ? v[7] : v[6]) + __shfl_xor_sync(F, b0 ? v[6] : v[7], 1);
    const bool b1 = lane & 2;
    float y03 = (b1 ? x23 : x01) + __shfl_xor_sync(F, b1 ? x01 : x23, 2);
    float y47 = (b1 ? x67 : x45) + __shfl_xor_sync(F, b1 ? x45 : x67, 2);
    const bool b2 = lane & 4;
    float z = (b2 ? y47 : y03) + __shfl_xor_sync(F, b2 ? y03 : y47, 4);
    z += __shfl_xor_sync(F, z, 8);
    z += __shfl_xor_sync(F, z, 16);
    return z;
}

__global__ __launch_bounds__(512, 2)
void slab_kernel(const float* __restrict__ x, float* __restrict__ out) {
    __shared__ float sBandRow[4][SLAB];
    __shared__ float sColPart[4][SZ];
    __shared__ float sCutM[SLAB];
    __shared__ float sCutA[SLAB];
    __shared__ float sSnapM[SLAB];
    __shared__ float sSnapA[SLAB];
    __shared__ float sDA[SLAB];
    __shared__ float cA1[SZ], cA2[SZ], cCT[SZ], cRT[SZ], cPM[SZ], cPA[SZ], cDAo[SZ];
    __shared__ bool amLast;

    const int blk = blockIdx.x;
    const int p = blk >> 2;
    const int s = blk & 3;
    const float* __restrict__ X = x + ((size_t)p * SZ + (size_t)s * SLAB) * SZ;

    const int tid  = threadIdx.x;
    const int w    = tid >> 5;
    const int lane = tid & 31;
    const int wr = w >> 2, wc = w & 3;
    const int c0  = wc * 128;
    const int lr0 = wr * 32;
    const bool mainRole = (wc == s);
    const bool antiRole = (wc == 3 - s);

    const float4* __restrict__ base =
        reinterpret_cast<const float4*>(X + (size_t)lr0 * SZ + c0) + lane;
    const int RS4 = SZ / 4;

    uint64_t acc01 = 0ull, acc23 = 0ull;

    // prime: group 0 loads
    float4 v[8];
#pragma unroll
    for (int u = 0; u < 8; u++)
        v[u] = __ldcs(base + u * RS4);

#pragma unroll
    for (int g = 0; g < 4; ++g) {
        const int lrg = lr0 + 8 * g;

        // ---- phase 1: consume v completely (cheap scalar work only) ----
        float sv[8];
#pragma unroll
        for (int u = 0; u < 8; u++) {
            uint64_t h = addf32x2(pack2(v[u].x, v[u].y), pack2(v[u].z, v[u].w));
            float lo, hi; unpack2(h, lo, hi);
            sv[u] = lo + hi;
        }

        float pk[8];                         // cut-element partial scalars (role warps)
        if (mainRole) {
            pk[0] = v[0].x;
            pk[1] = v[1].x + v[1].y;
            pk[2] = (v[2].x + v[2].y) + v[2].z;
            pk[3] = sv[3];
            pk[4] = v[4].x;
            pk[5] = v[5].x + v[5].y;
            pk[6] = (v[6].x + v[6].y) + v[6].z;
            pk[7] = sv[7];
        }
        if (antiRole) {
            pk[0] = sv[0];
            pk[1] = (v[1].x + v[1].y) + v[1].z;
            pk[2] = v[2].x + v[2].y;
            pk[3] = v[3].x;
            pk[4] = sv[4];
            pk[5] = (v[5].x + v[5].y) + v[5].z;
            pk[6] = v[6].x + v[6].y;
            pk[7] = v[7].x;
        }

        // snapshots (strict col prefixes, read acc BEFORE that row's update) + acc update
#pragma unroll
        for (int u = 0; u < 8; u++) {
            const int lr = lrg + u;
            if (mainRole) {
                const int ls = 8 * wr + 2 * g + (u >> 2);
                if (lane == ls) {
                    float lo, hi, sn;
                    if ((u & 3) < 2) { unpack2(acc01, lo, hi); sn = ((u & 3) == 0) ? lo : hi; }
                    else             { unpack2(acc23, lo, hi); sn = ((u & 3) == 2) ? lo : hi; }
                    sSnapM[lr] = sn;
                }
            }
            if (antiRole) {
                const int lsA = ((127 - lrg) >> 2) - (u >> 2);
                const int kA = 3 - (u & 3);
                if (lane == lsA) {
                    const float e = (kA == 0) ? v[u].x : (kA == 1) ? v[u].y
                                  : (kA == 2) ? v[u].z : v[u].w;
                    float lo, hi, sn;
                    if (kA < 2) { unpack2(acc01, lo, hi); sn = (kA == 0) ? lo : hi; }
                    else        { unpack2(acc23, lo, hi); sn = (kA == 2) ? lo : hi; }
                    sSnapA[127 - lr] = sn;
                    sDA[lr] = e;
                }
            }
            acc01 = addf32x2(acc01, pack2(v[u].x, v[u].y));
            acc23 = addf32x2(acc23, pack2(v[u].z, v[u].w));
        }

        // ---- phase 2: v is dead -> issue next group's loads NOW ----
        if (g < 3) {
#pragma unroll
            for (int u = 0; u < 8; u++)
                v[u] = __ldcs(base + ((g + 1) * 8 + u) * RS4);
        }

        // ---- phase 3: long shuffle chains (loads in flight underneath) ----
        const float r8 = multireduce8(sv, lane);
        if (lane < 8) sBandRow[wc][lrg + lane] = r8;

        if (mainRole) {
            const int ls0 = 8 * wr + 2 * g;
            const int ls1 = ls0 + 1;
            float m[8];
            {
                const bool lt = lane < ls0, eq = lane == ls0;
                m[0] = lt ? sv[0] : eq ? pk[0] : 0.f;
                m[1] = lt ? sv[1] : eq ? pk[1] : 0.f;
                m[2] = lt ? sv[2] : eq ? pk[2] : 0.f;
                m[3] = (lt | eq) ? sv[3] : 0.f;
            }
            {
                const bool lt = lane < ls1, eq = lane == ls1;
                m[4] = lt ? sv[4] : eq ? pk[4] : 0.f;
                m[5] = lt ? sv[5] : eq ? pk[5] : 0.f;
                m[6] = lt ? sv[6] : eq ? pk[6] : 0.f;
                m[7] = (lt | eq) ? sv[7] : 0.f;
            }
            const float mc = multireduce8(m, lane);
            if (lane < 8) sCutM[lrg + lane] = mc;
        }
        if (antiRole) {
            const int lsA0 = (127 - lrg) >> 2;
            const int lsA1 = lsA0 - 1;
            float m[8];
            {
                const bool lt = lane < lsA0, eq = lane == lsA0;
                m[0] = (lt | eq) ? sv[0] : 0.f;
                m[1] = lt ? sv[1] : eq ? pk[1] : 0.f;
                m[2] = lt ? sv[2] : eq ? pk[2] : 0.f;
                m[3] = lt ? sv[3] : eq ? pk[3] : 0.f;
            }
            {
                const bool lt = lane < lsA1, eq = lane == lsA1;
                m[4] = (lt | eq) ? sv[4] : 0.f;
                m[5] = lt ? sv[5] : eq ? pk[5] : 0.f;
                m[6] = lt ? sv[6] : eq ? pk[6] : 0.f;
                m[7] = lt ? sv[7] : eq ? pk[7] : 0.f;
            }
            const float mc = multireduce8(m, lane);
            if (lane < 8) sCutA[lrg + lane] = mc;
        }
    }

    {
        float a0, a1, a2, a3;
        unpack2(acc01, a0, a1);
        unpack2(acc23, a2, a3);
        reinterpret_cast<float4*>(&sColPart[wr][c0])[lane] = make_float4(a0, a1, a2, a3);
    }
    __syncthreads();

    // ---- slab combine: columns ----
    {
        const int c = tid;
        const float q0 = sColPart[0][c], q1 = sColPart[1][c],
                    q2 = sColPart[2][c], q3 = sColPart[3][c];
        g_colsum[p][s][c] = (q0 + q1) + (q2 + q3);

        const int band = c >> 7;
        if (band == s) {
            const int lr = c - 128 * s;
            const int rg = lr >> 5;
            float sn = sSnapM[lr];
            if (rg > 0) sn += q0;
            if (rg > 1) sn += q1;
            if (rg > 2) sn += q2;
            g_snapM[p][c] = sn;
        }
        if (band == 3 - s) {
            const int la = c - 128 * (3 - s);   // == 127 - lr
            const int rg = (127 - la) >> 5;
            float sn = sSnapA[la];
            if (rg > 0) sn += q0;
            if (rg > 1) sn += q1;
            if (rg > 2) sn += q2;
            g_snapA[p][c] = sn;
        }
    }
    // ---- slab combine: rows ----
    if (tid < SLAB) {
        const int lr = tid;
        const int gr = 128 * s + lr;
        const float b0 = sBandRow[0][lr], b1 = sBandRow[1][lr],
                    b2 = sBandRow[2][lr], b3 = sBandRow[3][lr];
        g_RT[p][gr] = (b0 + b1) + (b2 + b3);

        float pm = sCutM[lr];
        if (s > 0) pm += b0;
        if (s > 1) pm += b1;
        if (s > 2) pm += b2;
        g_PM[p][gr] = pm;

        const int ab = 3 - s;
        float pa = sCutA[lr];
        if (ab > 0) pa += b0;
        if (ab > 1) pa += b1;
        if (ab > 2) pa += b2;
        g_PA[p][gr] = pa;

        g_DA[p][gr] = sDA[lr];
    }

    // ---- last-block-per-plane fused combine ----
    __threadfence();
    __syncthreads();
    if (tid == 0) {
        const unsigned t = atomicAdd(&g_cnt[p], 1u);
        amLast = (t == 3u);
        if (amLast) g_cnt[p] = 0;
    }
    __syncthreads();
    if (!amLast) return;

    {
        const int i = tid;
        const float q0 = g_colsum[p][0][i], q1 = g_colsum[p][1][i],
                    q2 = g_colsum[p][2][i], q3 = g_colsum[p][3][i];
        cCT[i] = (q0 + q1) + (q2 + q3);

        const int jm = i >> 7;
        float a1 = g_snapM[p][i];
        if (jm > 0) a1 += q0;
        if (jm > 1) a1 += q1;
        if (jm > 2) a1 += q2;
        cA1[i] = a1;

        const int ja = (SZ - 1 - i) >> 7;
        float a2 = g_snapA[p][i];
        if (ja > 0) a2 += q0;
        if (ja > 1) a2 += q1;
        if (ja > 2) a2 += q2;
        cA2[i] = a2;

        cRT[i] = g_RT[p][i]; cPM[i] = g_PM[p][i]; cPA[i] = g_PA[p][i]; cDAo[i] = g_DA[p][i];
    }
    __syncthreads();
    {
        const int i = tid;
        const int m = SZ - 1 - i;

        const float tl = cPM[i] + cA1[i];
        const float tr = cRT[i] - cPA[i] + cDAo[i] + cA2[m];
        const float bl = cPA[m] + cCT[i] - cA2[i] - cDAo[m];
        const float br = cRT[m] - cPM[m] + cCT[m] - cA1[m];

        const float inv = 1.0f / (float)(2 * i + 1);
        const int b  = p >> 3;
        const int ch = p & 7;
        float* __restrict__ o = out + ((size_t)(b * SZ + i)) * 32 + ch;
        o[0]  = tl * inv;
        o[8]  = tr * inv;
        o[16] = bl * inv;
        o[24] = br * inv;
    }
}

extern "C" void kernel_launch(void* const* d_in, const int* in_sizes, int n_in,
                              void* d_out, int out_size) {
    const float* x = (const float*)d_in[0];
    float* out = (float*)d_out;
    const int planes = in_sizes[0] / (SZ * SZ);   // 256
    slab_kernel<<<planes * 4, 512>>>(x, out);
}